// round 7
// baseline (speedup 1.0000x reference)
#include <cuda_runtime.h>

// ---------------- problem constants ----------------
#define N_NODES 100000
#define N_EDGES 600000
#define IN_DIM  256
#define H0      128
#define H1      64
#define EPS_F   1e-5f

// ---------------- scratch (device globals; no allocs allowed) ----------------
__device__ __align__(16) float g_t  [(size_t)N_NODES * H0];   // GEMM output (pre-aggregation)
__device__ __align__(16) float g_h  [(size_t)N_NODES * H0];   // layer activation (post relu)
__device__ __align__(16) float g_norm[N_EDGES];
__device__ __align__(16) float g_deg [N_NODES];               // degree, then D^-1/2 in place
__device__ __align__(16) float g_stat[2 * IN_DIM];            // column sums / sumsq
__device__ __align__(16) float g_scale[IN_DIM];
__device__ __align__(16) float g_shift[IN_DIM];
__device__ __align__(16) float g_W0f [IN_DIM * H0];           // BN-folded W0
__device__ __align__(16) float g_kvec[H0];                    // c @ W0
__device__ __align__(16) float g_pWf [H0 * H1];               // BN-folded pW
__device__ __align__(16) float g_pbf [H1];                    // pb + c @ pW
// edge arrays (dtype-normalized) + CSR (dst-major), rebuilt every launch
__device__ __align__(16) int   g_src  [N_EDGES];
__device__ __align__(16) int   g_dst  [N_EDGES];
__device__ __align__(16) int   g_cnt  [N_NODES];
__device__ __align__(16) int   g_rowptr[N_NODES + 1];
__device__ __align__(16) int   g_cursor[N_NODES];
__device__ __align__(16) int   g_psrc  [N_EDGES];
__device__ __align__(16) float g_pnorm [N_EDGES];
__device__ int g_is64;

// ---------------- f32x2 helpers ----------------
__device__ __forceinline__ unsigned long long pack2(float lo, float hi) {
    unsigned long long d;
    asm("mov.b64 %0, {%1, %2};" : "=l"(d) : "f"(lo), "f"(hi));
    return d;
}
__device__ __forceinline__ void unpack2(unsigned long long d, float& lo, float& hi) {
    asm("mov.b64 {%0, %1}, %2;" : "=f"(lo), "=f"(hi) : "l"(d));
}
__device__ __forceinline__ unsigned long long ffma2(unsigned long long a,
                                                    unsigned long long b,
                                                    unsigned long long c) {
    unsigned long long d;
    asm("fma.rn.f32x2 %0, %1, %2, %3;" : "=l"(d) : "l"(a), "l"(b), "l"(c));
    return d;
}

// ---------------- utility kernels ----------------
__global__ void zero_kernel(float4* __restrict__ p, int n4) {
    int i = blockIdx.x * blockDim.x + threadIdx.x;
    if (i < n4) p[i] = make_float4(0.f, 0.f, 0.f, 0.f);
}

// Detect whether edge_index is int64 or int32. For int64, the high 32-bit
// word of every (nonnegative, < 2^31) value is 0. For random int32 node ids
// the probability that 512 consecutive odd words are all zero is ~0.
__global__ void detect_kernel(const int* __restrict__ w) {
    if (threadIdx.x == 0) {
        int all0 = 1;
        for (int i = 0; i < 512; i++)
            if (w[2 * i + 1] != 0) { all0 = 0; break; }
        g_is64 = all0;
    }
}

// Normalize edge indices into int arrays; accumulate weighted degree + counts.
__global__ void prep_kernel(const int* __restrict__ w,
                            const float* __restrict__ ew,
                            int* __restrict__ src, int* __restrict__ dst,
                            float* __restrict__ deg, int* __restrict__ cnt,
                            int E) {
    int t = blockIdx.x * blockDim.x + threadIdx.x;
    if (t >= E) return;
    int s, d;
    if (g_is64) {
        s = w[2 * t];
        d = w[2 * (E + t)];
    } else {
        s = w[t];
        d = w[E + t];
    }
    src[t] = s;
    dst[t] = d;
    atomicAdd(&deg[d], ew[t]);
    atomicAdd(&cnt[d], 1);
}

__global__ void dis_kernel(float* __restrict__ deg, int n) {
    int t = blockIdx.x * blockDim.x + threadIdx.x;
    if (t >= n) return;
    float d = deg[t];
    deg[t] = (d > 0.f) ? rsqrtf(fmaxf(d, EPS_F)) : 0.f;
}

__global__ void norm_kernel(const int* __restrict__ src,
                            const int* __restrict__ dst,
                            const float* __restrict__ ew,
                            const float* __restrict__ dis,
                            float* __restrict__ nrm, int E) {
    int t = blockIdx.x * blockDim.x + threadIdx.x;
    if (t >= E) return;
    nrm[t] = dis[src[t]] * ew[t] * dis[dst[t]];
}

// single-block exclusive scan over g_cnt -> g_rowptr/g_cursor
__global__ void scan_kernel(const int* __restrict__ cnt,
                            int* __restrict__ rowptr,
                            int* __restrict__ cursor) {
    __shared__ int part[1024];
    const int T = 1024;
    const int CH = (N_NODES + T - 1) / T;   // 98
    int t = threadIdx.x;
    int base = t * CH;
    int s = 0;
    for (int i = 0; i < CH; i++) {
        int idx = base + i;
        if (idx < N_NODES) s += cnt[idx];
    }
    part[t] = s;
    __syncthreads();
    for (int off = 1; off < T; off <<= 1) {
        int v = (t >= off) ? part[t - off] : 0;
        __syncthreads();
        part[t] += v;
        __syncthreads();
    }
    int run = (t == 0) ? 0 : part[t - 1];
    for (int i = 0; i < CH; i++) {
        int idx = base + i;
        if (idx < N_NODES) {
            rowptr[idx] = run;
            cursor[idx] = run;
            run += cnt[idx];
        }
    }
    if (t == 0) rowptr[N_NODES] = N_EDGES;
}

__global__ void scatter_kernel(const int* __restrict__ src,
                               const int* __restrict__ dst,
                               const float* __restrict__ nrm,
                               int* __restrict__ cursor,
                               int* __restrict__ psrc,
                               float* __restrict__ pnorm, int E) {
    int t = blockIdx.x * blockDim.x + threadIdx.x;
    if (t >= E) return;
    int pos = atomicAdd(&cursor[dst[t]], 1);
    psrc[pos]  = src[t];
    pnorm[pos] = nrm[t];
}

// per-column sum / sumsq via block-local accumulation + atomics
template <int C>
__global__ void bnstats_kernel(const float* __restrict__ X,
                               float* __restrict__ stat,
                               int M, int rowsPerBlock) {
    int col = threadIdx.x;           // blockDim.x == C
    int r0 = blockIdx.x * rowsPerBlock;
    int r1 = min(r0 + rowsPerBlock, M);
    float s = 0.f, s2 = 0.f;
    for (int r = r0; r < r1; r++) {
        float v = X[(size_t)r * C + col];
        s += v; s2 += v * v;
    }
    atomicAdd(&stat[col], s);
    atomicAdd(&stat[C + col], s2);
}

template <int C>
__global__ void bnscale_kernel(const float* __restrict__ stat,
                               const float* __restrict__ gamma,
                               const float* __restrict__ beta,
                               float* __restrict__ scale,
                               float* __restrict__ shift, float invM) {
    int c = threadIdx.x;
    float mean = stat[c] * invM;
    float var  = stat[C + c] * invM - mean * mean;
    float a = gamma[c] * rsqrtf(var + EPS_F);
    scale[c] = a;
    shift[c] = beta[c] - mean * a;
}

// Wf[j,k] = scale[j]*W[j,k];  bout[k] = baseBias[k] + sum_j shift[j]*W[j,k]
template <int KIN, int NOUT>
__global__ void fold_kernel(const float* __restrict__ W,
                            const float* __restrict__ scale,
                            const float* __restrict__ shift,
                            const float* __restrict__ baseBias,
                            float* __restrict__ Wf,
                            float* __restrict__ bout) {
    __shared__ float red[KIN];
    int k = blockIdx.x;      // output column
    int j = threadIdx.x;     // input row   (blockDim.x == KIN)
    float w = W[(size_t)j * NOUT + k];
    Wf[(size_t)j * NOUT + k] = scale[j] * w;
    red[j] = shift[j] * w;
    __syncthreads();
    for (int s = KIN / 2; s > 0; s >>= 1) {
        if (j < s) red[j] += red[j + s];
        __syncthreads();
    }
    if (j == 0) bout[k] = red[0] + (baseBias ? baseBias[k] : 0.f);
}

// ---------------- fused CSR aggregation + bias + relu ----------------
// one warp per destination node, lane owns 4 contiguous columns (H0=128)
__global__ __launch_bounds__(256)
void aggbr_kernel(const float* __restrict__ hin,
                  const int* __restrict__ rowptr,
                  const int* __restrict__ psrc,
                  const float* __restrict__ pnorm,
                  const float* __restrict__ bias,
                  float* __restrict__ out) {
    int node = blockIdx.x * (blockDim.x >> 5) + (threadIdx.x >> 5);
    if (node >= N_NODES) return;
    int lane = threadIdx.x & 31;
    int j0 = rowptr[node], j1 = rowptr[node + 1];
    float ax = 0.f, ay = 0.f, az = 0.f, aw = 0.f;
    for (int j = j0; j < j1; j++) {
        int   s = __ldg(psrc + j);
        float c = __ldg(pnorm + j);
        float4 v = *(const float4*)(hin + (size_t)s * H0 + lane * 4);
        ax = fmaf(c, v.x, ax);
        ay = fmaf(c, v.y, ay);
        az = fmaf(c, v.z, az);
        aw = fmaf(c, v.w, aw);
    }
    float4 b = *(const float4*)(bias + lane * 4);
    float4 o;
    o.x = fmaxf(ax + b.x, 0.f);
    o.y = fmaxf(ay + b.y, 0.f);
    o.z = fmaxf(az + b.z, 0.f);
    o.w = fmaxf(aw + b.w, 0.f);
    *(float4*)(out + (size_t)node * H0 + lane * 4) = o;
}

// ---------------- fp32x2 GEMM: C[M,NC] = A[M,K] @ W[K,NC] (+addvec) (+relu) ----------------
// block: 64 rows x NC cols, 256 threads, thread micro-tile 4 x (NC/16)
template <int K, int NC, bool RELU>
__global__ __launch_bounds__(256)
void gemm_kernel(const float* __restrict__ A, const float* __restrict__ W,
                 const float* __restrict__ addvec, float* __restrict__ C, int M) {
    constexpr int TM = 64, TK = 32;
    constexpr int CPT = NC / 16;      // cols per thread: 8 or 4
    constexpr int CP2 = CPT / 2;      // f32x2 pairs per thread

    __shared__ __align__(16) float As[TK][TM + 4];  // transposed A tile
    __shared__ __align__(16) float Ws[TK][NC];

    int tid = threadIdx.x;
    int tn = tid & 15;                // column group
    int tm = tid >> 4;                // row group (0..15)
    int rowBase = blockIdx.x * TM;

    unsigned long long acc[4][CP2];
#pragma unroll
    for (int r = 0; r < 4; r++)
#pragma unroll
        for (int c = 0; c < CP2; c++) acc[r][c] = 0ull;

    int la_r = tid >> 3;              // 0..31 (two passes cover 64 rows)
    int la_k = (tid & 7) * 4;
    constexpr int WF4 = NC / 4;       // float4 per Ws row
    constexpr int RPP = 256 / WF4;    // Ws rows per pass
    int wc4 = tid % WF4;
    int wr0 = tid / WF4;

    for (int k0 = 0; k0 < K; k0 += TK) {
        // load A tile (transposed into smem)
#pragma unroll
        for (int i = 0; i < 2; i++) {
            int r = la_r + i * 32;
            int grow = rowBase + r;
            float4 v = (grow < M)
                ? *(const float4*)(A + (size_t)grow * K + k0 + la_k)
                : make_float4(0.f, 0.f, 0.f, 0.f);
            As[la_k + 0][r] = v.x;
            As[la_k + 1][r] = v.y;
            As[la_k + 2][r] = v.z;
            As[la_k + 3][r] = v.w;
        }
        // load W tile (row-major, coalesced)
#pragma unroll
        for (int r = wr0; r < TK; r += RPP) {
            *(float4*)&Ws[r][wc4 * 4] =
                *(const float4*)(W + (size_t)(k0 + r) * NC + wc4 * 4);
        }
        __syncthreads();

#pragma unroll
        for (int kk = 0; kk < TK; kk++) {
            float4 av = *(const float4*)&As[kk][tm * 4];
            unsigned long long pa[4];
            pa[0] = pack2(av.x, av.x);
            pa[1] = pack2(av.y, av.y);
            pa[2] = pack2(av.z, av.z);
            pa[3] = pack2(av.w, av.w);
            const unsigned long long* wp =
                (const unsigned long long*)&Ws[kk][tn * CPT];
            unsigned long long wv[CP2];
#pragma unroll
            for (int c = 0; c < CP2; c++) wv[c] = wp[c];
#pragma unroll
            for (int r = 0; r < 4; r++)
#pragma unroll
                for (int c = 0; c < CP2; c++)
                    acc[r][c] = ffma2(pa[r], wv[c], acc[r][c]);
        }
        __syncthreads();
    }

    // epilogue
#pragma unroll
    for (int r = 0; r < 4; r++) {
        int grow = rowBase + tm * 4 + r;
        if (grow >= M) continue;
        float o[CPT];
#pragma unroll
        for (int c = 0; c < CP2; c++) unpack2(acc[r][c], o[2 * c], o[2 * c + 1]);
        if (addvec) {
#pragma unroll
            for (int i = 0; i < CPT; i++) o[i] += __ldg(addvec + tn * CPT + i);
        }
        if (RELU) {
#pragma unroll
            for (int i = 0; i < CPT; i++) o[i] = fmaxf(o[i], 0.f);
        }
        float* cp = C + (size_t)grow * NC + tn * CPT;
        *(float4*)cp = make_float4(o[0], o[1], o[2], o[3]);
        if (CPT == 8)
            *(float4*)(cp + 4) = make_float4(o[4], o[5], o[6], o[7]);
    }
}

// ---------------- launch ----------------
extern "C" void kernel_launch(void* const* d_in, const int* in_sizes, int n_in,
                              void* d_out, int out_size) {
    const float* x   = (const float*)d_in[0];
    const int*   eiw = (const int*)d_in[1];     // edge_index raw words (dtype detected)
    const float* ew  = (const float*)d_in[2];
    const float* bng = (const float*)d_in[3];
    const float* bnb = (const float*)d_in[4];
    const float* W0  = (const float*)d_in[5];
    const float* b0  = (const float*)d_in[6];
    const float* W1  = (const float*)d_in[7];
    const float* b1  = (const float*)d_in[8];
    const float* W2  = (const float*)d_in[9];
    const float* b2  = (const float*)d_in[10];
    const float* pg  = (const float*)d_in[11];
    const float* pbb = (const float*)d_in[12];
    const float* pW  = (const float*)d_in[13];
    const float* pb  = (const float*)d_in[14];
    float* out = (float*)d_out;

    float *t_, *h_, *norm_, *deg_, *stat_, *sc_, *sh_, *W0f_, *kvec_, *pWf_, *pbf_, *pnorm_;
    int *src_, *dst_, *cnt_, *rowptr_, *cursor_, *psrc_;
    cudaGetSymbolAddress((void**)&t_,     g_t);
    cudaGetSymbolAddress((void**)&h_,     g_h);
    cudaGetSymbolAddress((void**)&norm_,  g_norm);
    cudaGetSymbolAddress((void**)&deg_,   g_deg);
    cudaGetSymbolAddress((void**)&stat_,  g_stat);
    cudaGetSymbolAddress((void**)&sc_,    g_scale);
    cudaGetSymbolAddress((void**)&sh_,    g_shift);
    cudaGetSymbolAddress((void**)&W0f_,   g_W0f);
    cudaGetSymbolAddress((void**)&kvec_,  g_kvec);
    cudaGetSymbolAddress((void**)&pWf_,   g_pWf);
    cudaGetSymbolAddress((void**)&pbf_,   g_pbf);
    cudaGetSymbolAddress((void**)&src_,   g_src);
    cudaGetSymbolAddress((void**)&dst_,   g_dst);
    cudaGetSymbolAddress((void**)&cnt_,   g_cnt);
    cudaGetSymbolAddress((void**)&rowptr_,g_rowptr);
    cudaGetSymbolAddress((void**)&cursor_,g_cursor);
    cudaGetSymbolAddress((void**)&psrc_,  g_psrc);
    cudaGetSymbolAddress((void**)&pnorm_, g_pnorm);

    const int E = N_EDGES, N = N_NODES;
    const int gemmBlocks = (N + 63) / 64;
    const int aggBlocks  = (N * 32 + 255) / 256;   // warp per node
    const int statRows   = 500;
    const int statGrid   = (N + statRows - 1) / statRows;

    // --- edge dtype normalization + graph normalization + CSR build ---
    detect_kernel<<<1, 32>>>(eiw);
    zero_kernel<<<(N / 4 + 255) / 256, 256>>>((float4*)deg_, N / 4);
    zero_kernel<<<(N / 4 + 255) / 256, 256>>>((float4*)cnt_, N / 4);
    prep_kernel<<<(E + 255) / 256, 256>>>(eiw, ew, src_, dst_, deg_, cnt_, E);
    dis_kernel<<<(N + 255) / 256, 256>>>(deg_, N);
    norm_kernel<<<(E + 255) / 256, 256>>>(src_, dst_, ew, deg_, norm_, E);
    scan_kernel<<<1, 1024>>>(cnt_, rowptr_, cursor_);
    scatter_kernel<<<(E + 255) / 256, 256>>>(src_, dst_, norm_, cursor_, psrc_, pnorm_, E);

    // --- BN(x) folded into W0 ---
    zero_kernel<<<1, 128>>>((float4*)stat_, 2 * IN_DIM / 4);
    bnstats_kernel<IN_DIM><<<statGrid, IN_DIM>>>(x, stat_, N, statRows);
    bnscale_kernel<IN_DIM><<<1, IN_DIM>>>(stat_, bng, bnb, sc_, sh_, 1.f / N);
    fold_kernel<IN_DIM, H0><<<H0, IN_DIM>>>(W0, sc_, sh_, nullptr, W0f_, kvec_);

    // --- layer 0: transform then fused aggregate+bias+relu ---
    gemm_kernel<IN_DIM, H0, false><<<gemmBlocks, 256>>>(x, W0f_, kvec_, t_, N);
    aggbr_kernel<<<aggBlocks, 256>>>(t_, rowptr_, psrc_, pnorm_, b0, h_);

    // --- layer 1 ---
    gemm_kernel<H0, H0, false><<<gemmBlocks, 256>>>(h_, W1, nullptr, t_, N);
    aggbr_kernel<<<aggBlocks, 256>>>(t_, rowptr_, psrc_, pnorm_, b1, h_);

    // --- layer 2 ---
    gemm_kernel<H0, H0, false><<<gemmBlocks, 256>>>(h_, W2, nullptr, t_, N);
    aggbr_kernel<<<aggBlocks, 256>>>(t_, rowptr_, psrc_, pnorm_, b2, h_);

    // --- projection head: BN folded into pW, then fused linear+relu ---
    zero_kernel<<<1, 64>>>((float4*)stat_, 2 * H0 / 4);
    bnstats_kernel<H0><<<statGrid, H0>>>(h_, stat_, N, statRows);
    bnscale_kernel<H0><<<1, H0>>>(stat_, pg, pbb, sc_, sh_, 1.f / N);
    fold_kernel<H0, H1><<<H1, H0>>>(pW, sc_, sh_, pb, pWf_, pbf_);
    gemm_kernel<H0, H1, true><<<gemmBlocks, 256>>>(h_, pWf_, pbf_, out, N);
}